// round 14
// baseline (speedup 1.0000x reference)
#include <cuda_runtime.h>
#include <cuda_fp16.h>
#include <cstdint>

#define NB    32
#define CIN   64
#define COUT  128
#define HDIM  64
#define WDIM  64
#define EPSV  1e-8f
#define FM_OFF (NB * COUT * HDIM * WDIM)
#define NT4   8192                // tiles: 32 n * 16 ty * 16 tx (4x4 outputs)
#define NPOS  36
#define WSC   256.0f              // weight plane scale
#define IWSC  0.00390625f         // 1/256

// ---- scratch (static __device__, no allocations) ----
__device__ float g_inv_norm[COUT];
__device__ __align__(128) __half g_Xh[NPOS][NT4][64];   // [pos][tile][ci]
__device__ __align__(128) __half g_Xl[NPOS][NT4][64];
__device__ __align__(128) __half g_Wh[NPOS][64][128];   // [pos][ci][co], x256
__device__ __align__(128) __half g_Wl[NPOS][64][128];

// output transform A^T rows (F(4,3))
__device__ const float cAT[4][6] = {
    {1.f, 1.f, 1.f, 1.f, 1.f, 0.f},
    {0.f, 1.f, -1.f, 2.f, -2.f, 0.f},
    {0.f, 1.f, 1.f, 4.f, 4.f, 0.f},
    {0.f, 1.f, -1.f, 8.f, -8.f, 1.f}};

// ---- helpers ----
__device__ __forceinline__ void cpa16(uint32_t dst, const void* src) {
    asm volatile("cp.async.ca.shared.global [%0], [%1], 16;" :: "r"(dst), "l"(src));
}
__device__ __forceinline__ void cpcommit() {
    asm volatile("cp.async.commit_group;" ::: "memory");
}
template <int N>
__device__ __forceinline__ void cpwait() {
    asm volatile("cp.async.wait_group %0;" :: "n"(N) : "memory");
}
__device__ __forceinline__ void ldsm_x4(uint32_t* r, uint32_t a) {
    asm volatile("ldmatrix.sync.aligned.m8n8.x4.shared.b16 {%0,%1,%2,%3}, [%4];"
                 : "=r"(r[0]), "=r"(r[1]), "=r"(r[2]), "=r"(r[3]) : "r"(a));
}
__device__ __forceinline__ void ldsm_x2t(uint32_t* r, uint32_t a) {
    asm volatile("ldmatrix.sync.aligned.m8n8.x2.trans.shared.b16 {%0,%1}, [%2];"
                 : "=r"(r[0]), "=r"(r[1]) : "r"(a));
}
__device__ __forceinline__ void mma16(float* d, const uint32_t* a, uint32_t b0,
                                      uint32_t b1) {
    asm volatile(
        "mma.sync.aligned.m16n8k16.row.col.f32.f16.f16.f32 "
        "{%0,%1,%2,%3},{%4,%5,%6,%7},{%8,%9},{%0,%1,%2,%3};"
        : "+f"(d[0]), "+f"(d[1]), "+f"(d[2]), "+f"(d[3])
        : "r"(a[0]), "r"(a[1]), "r"(a[2]), "r"(a[3]), "r"(b0), "r"(b1));
}

// ---------- prep: per-Cout 1/(||k||^2 + eps) ----------
__global__ void prep_norm(const float* __restrict__ kern) {
    __shared__ float red[512];
    int t = threadIdx.x;
    int co = t & 127;
    int part = t >> 7;
    float s = 0.f;
#pragma unroll 4
    for (int i = part * 144; i < part * 144 + 144; i++) {
        float v = kern[i * COUT + co];
        s += v * v;
    }
    red[t] = s;
    __syncthreads();
    if (t < 128)
        g_inv_norm[co] = 1.f / (red[co] + red[co + 128] + red[co + 256] + red[co + 384] + EPSV);
}

// ---------- prep: F(4,3) weight transform W~ = (G g G^T) * 256, fp16 hi/lo ----------
__global__ void prep_Wt(const float* __restrict__ kern) {
    int id = blockIdx.x * 256 + threadIdx.x;   // 8192
    int co = id & 127;
    int ci = id >> 7;

    float g[3][3];
#pragma unroll
    for (int kh = 0; kh < 3; kh++)
#pragma unroll
        for (int kw = 0; kw < 3; kw++)
            g[kh][kw] = kern[(kh * 3 + kw) * (CIN * COUT) + ci * COUT + co];

    float t[6][3];
#pragma unroll
    for (int c = 0; c < 3; c++) {
        t[0][c] = 0.25f * g[0][c];
        t[1][c] = -(g[0][c] + g[1][c] + g[2][c]) * (1.f / 6.f);
        t[2][c] = (-g[0][c] + g[1][c] - g[2][c]) * (1.f / 6.f);
        t[3][c] = g[0][c] * (1.f / 24.f) + g[1][c] * (1.f / 12.f) + g[2][c] * (1.f / 6.f);
        t[4][c] = g[0][c] * (1.f / 24.f) - g[1][c] * (1.f / 12.f) + g[2][c] * (1.f / 6.f);
        t[5][c] = g[2][c];
    }
#pragma unroll
    for (int i = 0; i < 6; i++) {
        float w[6];
        w[0] = 0.25f * t[i][0];
        w[1] = -(t[i][0] + t[i][1] + t[i][2]) * (1.f / 6.f);
        w[2] = (-t[i][0] + t[i][1] - t[i][2]) * (1.f / 6.f);
        w[3] = t[i][0] * (1.f / 24.f) + t[i][1] * (1.f / 12.f) + t[i][2] * (1.f / 6.f);
        w[4] = t[i][0] * (1.f / 24.f) - t[i][1] * (1.f / 12.f) + t[i][2] * (1.f / 6.f);
        w[5] = t[i][2];
#pragma unroll
        for (int j = 0; j < 6; j++) {
            int p = i * 6 + j;
            float v = w[j] * WSC;
            __half h = __float2half(v);
            __half l = __float2half(v - __half2float(h));
            g_Wh[p][ci][co] = h;
            g_Wl[p][ci][co] = l;
        }
    }
}

// ---------- prep: F(4,3) input transform X~ = B^T d B, smem-staged, ci-pair/thread ----
#define XSP4 66
#define XT4_SMEM (6 * 64 * XSP4 * 4)
__global__ __launch_bounds__(256)
void prep_Xt(const float* __restrict__ x) {
    extern __shared__ float xs[];
    const int n = blockIdx.x >> 4;
    const int ty = blockIdx.x & 15;
    const int tid = threadIdx.x;
    const int w = tid >> 5;
    const int l = tid & 31;           // ci pair (2l, 2l+1)

#pragma unroll
    for (int i = 0; i < 96; i++) {
        int idx = tid + i * 256;
        int ci = idx / 384;
        int rem = idx - ci * 384;
        int r = rem >> 6;
        int c = rem & 63;
        int gr = 4 * ty - 1 + r;
        float v = (gr >= 0 && gr < HDIM)
                      ? __ldg(x + ((n * CIN + ci) * HDIM + gr) * WDIM + c)
                      : 0.f;
        xs[(r * 64 + c) * XSP4 + ci] = v;
    }
    __syncthreads();

#pragma unroll 1
    for (int it = 0; it < 2; it++) {
        const int tx = it * 8 + w;
        const int tile = n * 256 + ty * 16 + tx;
        const int wb = 4 * tx - 1;

        float2 s[6][6];
#pragma unroll
        for (int c = 0; c < 6; c++) {
            int gc = wb + c;
            float2 d0 = make_float2(0.f, 0.f), d1 = d0, d2 = d0, d3 = d0, d4 = d0, d5 = d0;
            if (gc >= 0 && gc < WDIM) {
                const float* colp = &xs[gc * XSP4 + 2 * l];
                d0 = *(const float2*)(colp + 0 * 64 * XSP4);
                d1 = *(const float2*)(colp + 1 * 64 * XSP4);
                d2 = *(const float2*)(colp + 2 * 64 * XSP4);
                d3 = *(const float2*)(colp + 3 * 64 * XSP4);
                d4 = *(const float2*)(colp + 4 * 64 * XSP4);
                d5 = *(const float2*)(colp + 5 * 64 * XSP4);
            }
            s[0][c].x = 4.f * d0.x - 5.f * d2.x + d4.x;
            s[0][c].y = 4.f * d0.y - 5.f * d2.y + d4.y;
            s[1][c].x = -4.f * d1.x - 4.f * d2.x + d3.x + d4.x;
            s[1][c].y = -4.f * d1.y - 4.f * d2.y + d3.y + d4.y;
            s[2][c].x = 4.f * d1.x - 4.f * d2.x - d3.x + d4.x;
            s[2][c].y = 4.f * d1.y - 4.f * d2.y - d3.y + d4.y;
            s[3][c].x = -2.f * d1.x - d2.x + 2.f * d3.x + d4.x;
            s[3][c].y = -2.f * d1.y - d2.y + 2.f * d3.y + d4.y;
            s[4][c].x = 2.f * d1.x - d2.x - 2.f * d3.x + d4.x;
            s[4][c].y = 2.f * d1.y - d2.y - 2.f * d3.y + d4.y;
            s[5][c].x = 4.f * d1.x - 5.f * d3.x + d5.x;
            s[5][c].y = 4.f * d1.y - 5.f * d3.y + d5.y;
        }
#pragma unroll
        for (int i = 0; i < 6; i++) {
#pragma unroll
            for (int j = 0; j < 6; j++) {
                float vx, vy;
                switch (j) {
                    case 0: vx = 4.f * s[i][0].x - 5.f * s[i][2].x + s[i][4].x;
                            vy = 4.f * s[i][0].y - 5.f * s[i][2].y + s[i][4].y; break;
                    case 1: vx = -4.f * s[i][1].x - 4.f * s[i][2].x + s[i][3].x + s[i][4].x;
                            vy = -4.f * s[i][1].y - 4.f * s[i][2].y + s[i][3].y + s[i][4].y; break;
                    case 2: vx = 4.f * s[i][1].x - 4.f * s[i][2].x - s[i][3].x + s[i][4].x;
                            vy = 4.f * s[i][1].y - 4.f * s[i][2].y - s[i][3].y + s[i][4].y; break;
                    case 3: vx = -2.f * s[i][1].x - s[i][2].x + 2.f * s[i][3].x + s[i][4].x;
                            vy = -2.f * s[i][1].y - s[i][2].y + 2.f * s[i][3].y + s[i][4].y; break;
                    case 4: vx = 2.f * s[i][1].x - s[i][2].x - 2.f * s[i][3].x + s[i][4].x;
                            vy = 2.f * s[i][1].y - s[i][2].y - 2.f * s[i][3].y + s[i][4].y; break;
                    default: vx = 4.f * s[i][1].x - 5.f * s[i][3].x + s[i][5].x;
                             vy = 4.f * s[i][1].y - 5.f * s[i][3].y + s[i][5].y; break;
                }
                int p = i * 6 + j;
                __half hx = __float2half(vx);
                __half lx = __float2half(vx - __half2float(hx));
                __half hy = __float2half(vy);
                __half ly = __float2half(vy - __half2float(hy));
                uint32_t hp = (uint32_t)__half_as_ushort(hx) |
                              ((uint32_t)__half_as_ushort(hy) << 16);
                uint32_t lp = (uint32_t)__half_as_ushort(lx) |
                              ((uint32_t)__half_as_ushort(ly) << 16);
                ((uint32_t*)g_Xh[p][tile])[l] = hp;
                ((uint32_t*)g_Xl[p][tile])[l] = lp;
            }
        }
    }
}

// ---------- fused: GEMM over 36 pos + per-pos fold + LIF/spike epilogue ----------
// CTA = 32 tiles x 32 co. grid 1024 = 256 tile-blocks x 4 co-blocks.
// smem union: gemm buffers 2x19456 [0,38912) ; epilogue slab 32x520 floats (66560 B)
// buffer layout: Ah +0 (32x144B), Al +4608, Bh +9216 (64x80B), Bl +14336
#define BUFB4  19456
#define SLABP  520
#define FUS_SMEM (32 * SLABP * 4)
__global__ __launch_bounds__(256, 2)
void wino_fused(const float* __restrict__ mem, const float* __restrict__ beta_p,
                const float* __restrict__ b_p, float* __restrict__ out) {
    extern __shared__ float slab[];
    const uint32_t smu = (uint32_t)__cvta_generic_to_shared(slab);

    const int tid = threadIdx.x;
    const int lane = tid & 31;
    const int wrp = tid >> 5;
    const int mw = wrp & 1;           // M half: tiles mw*16..+15
    const int nw = wrp >> 1;          // N group: co nw*8..+7
    const int bid = blockIdx.x;
    const int cob = bid & 3;          // co block (32 co)
    const int TB = (bid >> 2) * 32;   // tile base
    const int n = TB >> 8;
    const int ty0 = (TB >> 4) & 15;   // even

    const int r0 = lane >> 2;
    const int c0 = 2 * (lane & 3);

#define STAGE4(p, buf)                                                          \
    {                                                                           \
        const int pp = (p);                                                     \
        uint32_t base = smu + (buf)*BUFB4;                                      \
        _Pragma("unroll")                                                       \
        for (int i = 0; i < 2; i++) {   /* A: 512 chunks */                     \
            int idx = tid + i * 256;                                            \
            int pl = idx >> 8;                                                  \
            int q = idx & 255;                                                  \
            int row = q >> 3, c = q & 7;                                        \
            cpa16(base + pl * 4608 + row * 144 + c * 16,                        \
                  (pl ? g_Xl[pp][TB + row] : g_Xh[pp][TB + row]) + c * 8);      \
        }                                                                       \
        _Pragma("unroll")                                                       \
        for (int i = 0; i < 2; i++) {   /* B: 512 chunks */                     \
            int idx = tid + i * 256;                                            \
            int pl = idx >> 8;                                                  \
            int q = idx & 255;                                                  \
            int row = q >> 2, c = q & 3;                                        \
            cpa16(base + 9216 + pl * 5120 + row * 80 + c * 16,                  \
                  (pl ? g_Wl[pp][row] : g_Wh[pp][row]) + cob * 32 + c * 8);     \
        }                                                                       \
    }

    float acc[16][4];
#pragma unroll
    for (int q = 0; q < 16; q++)
#pragma unroll
        for (int f = 0; f < 4; f++) acc[q][f] = 0.f;

    const uint32_t aoff =
        (uint32_t)(mw * 16 + (lane & 15)) * 144 + (uint32_t)(lane >> 4) * 16;
    const uint32_t boff = (uint32_t)(lane & 15) * 80 + (uint32_t)(nw * 8) * 2;

    STAGE4(0, 0);
    cpcommit();

#pragma unroll 1
    for (int p = 0; p < NPOS; p++) {
        const int buf = p & 1;
        cpwait<0>();
        __syncthreads();
        if (p < NPOS - 1) {
            STAGE4(p + 1, buf ^ 1);
            cpcommit();
        }

        const uint32_t Ab = smu + buf * BUFB4;
        float m[4] = {0.f, 0.f, 0.f, 0.f};
#pragma unroll
        for (int kb = 0; kb < 4; kb++) {
            uint32_t aAddr = Ab + aoff + kb * 32;
            uint32_t bAddr = Ab + 9216 + (uint32_t)(kb * 16) * 80 + boff;
            uint32_t ah[4], al[4], bh[2], bl[2];
            ldsm_x4(ah, aAddr);
            ldsm_x4(al, aAddr + 4608);
            ldsm_x2t(bh, bAddr);
            ldsm_x2t(bl, bAddr + 5120);
            mma16(m, ah, bh[0], bh[1]);
            mma16(m, al, bh[0], bh[1]);
            mma16(m, ah, bl[0], bl[1]);
            mma16(m, al, bl[0], bl[1]);
        }

        // fold into 16 output accumulators
        const int fi = p / 6, fj = p - fi * 6;
        float ar[4], ac[4];
#pragma unroll
        for (int r = 0; r < 4; r++) {
            ar[r] = cAT[r][fi];
            ac[r] = cAT[r][fj];
        }
#pragma unroll
        for (int r = 0; r < 4; r++)
#pragma unroll
            for (int c = 0; c < 4; c++) {
                float dq = ar[r] * ac[c];
#pragma unroll
                for (int f = 0; f < 4; f++) acc[r * 4 + c][f] += dq * m[f];
            }
    }

    // ---- epilogue: LIF + multi-threshold spike via smem slab ----
    __syncthreads();    // buffers dead; slab reuses the same smem

    const int memBase = (n * COUT + cob * 32) * (HDIM * WDIM) + ty0 * 4 * WDIM;

    // E1: stage mem slab (coalesced): [co 32][8h x 64w = 512]
#pragma unroll
    for (int i = 0; i < 64; i++) {
        int idx = tid + i * 256;
        int cl = idx >> 9;
        int rest = idx & 511;
        slab[cl * SLABP + rest] = __ldg(mem + memBase + cl * (HDIM * WDIM) + rest);
    }
    __syncthreads();

    const float beta = beta_p[0];
    const float omb = 1.f - beta;
    float invn2[2], bb2[2];
#pragma unroll
    for (int cs = 0; cs < 2; cs++) {
        int co = cob * 32 + nw * 8 + c0 + cs;
        invn2[cs] = g_inv_norm[co];
        bb2[cs] = __ldg(b_p + co);
    }

    // E2: LIF in place; spk -> slab, fm -> acc
#pragma unroll
    for (int f = 0; f < 4; f++) {
        const int tl = mw * 16 + r0 + (f >> 1) * 8;
        const int cl = nw * 8 + c0 + (f & 1);
        const int tyo = tl >> 4;
        const int tx = tl & 15;
        const int bs = cl * SLABP + tyo * 256 + tx * 4;
        const float invn = invn2[f & 1];
        const float bb = bb2[f & 1];
#pragma unroll
        for (int r = 0; r < 4; r++)
#pragma unroll
            for (int c = 0; c < 4; c++) {
                int si = bs + r * 64 + c;
                float conv = acc[r * 4 + c][f] * IWSC;
                float nm = slab[si] * beta + conv * omb;
                float mt = nm * invn - bb;
                float cnt = (float)((mt > 0.f) + (mt > 1.f) + (mt > 2.f) + (mt > 3.f));
                slab[si] = cnt;
                acc[r * 4 + c][f] = (cnt > 0.f) ? 0.f : nm;
            }
    }
    __syncthreads();

    // E3: stream spk plane
#pragma unroll
    for (int i = 0; i < 16; i++) {
        int idx = tid + i * 256;
        int cl = idx >> 7;
        int r4 = idx & 127;
        float4 v = *(float4*)&slab[cl * SLABP + r4 * 4];
        *(float4*)(out + memBase + cl * (HDIM * WDIM) + r4 * 4) = v;
    }
    __syncthreads();

    // E4: write fm into slab
#pragma unroll
    for (int f = 0; f < 4; f++) {
        const int tl = mw * 16 + r0 + (f >> 1) * 8;
        const int cl = nw * 8 + c0 + (f & 1);
        const int tyo = tl >> 4;
        const int tx = tl & 15;
        const int bs = cl * SLABP + tyo * 256 + tx * 4;
#pragma unroll
        for (int r = 0; r < 4; r++)
#pragma unroll
            for (int c = 0; c < 4; c++)
                slab[bs + r * 64 + c] = acc[r * 4 + c][f];
    }
    __syncthreads();

    // E5: stream fm plane
#pragma unroll
    for (int i = 0; i < 16; i++) {
        int idx = tid + i * 256;
        int cl = idx >> 7;
        int r4 = idx & 127;
        float4 v = *(float4*)&slab[cl * SLABP + r4 * 4];
        *(float4*)(out + FM_OFF + memBase + cl * (HDIM * WDIM) + r4 * 4) = v;
    }
}

extern "C" void kernel_launch(void* const* d_in, const int* in_sizes, int n_in,
                              void* d_out, int out_size) {
    const float* x    = (const float*)d_in[0];
    const float* mem  = (const float*)d_in[1];
    const float* kern = (const float*)d_in[2];
    const float* beta = (const float*)d_in[3];
    const float* b    = (const float*)d_in[4];
    float* out = (float*)d_out;

    cudaFuncSetAttribute(prep_Xt, cudaFuncAttributeMaxDynamicSharedMemorySize, XT4_SMEM);
    cudaFuncSetAttribute(wino_fused, cudaFuncAttributeMaxDynamicSharedMemorySize,
                         FUS_SMEM);

    prep_norm<<<1, 512>>>(kern);
    prep_Wt<<<32, 256>>>(kern);
    prep_Xt<<<512, 256, XT4_SMEM>>>(x);
    wino_fused<<<1024, 256, FUS_SMEM>>>(mem, beta, b, out);
}